// round 12
// baseline (speedup 1.0000x reference)
#include <cuda_runtime.h>
#include <cuda_bf16.h>
#include <cstdint>

// ================= helpers ==================================================
__device__ __forceinline__ uint32_t smem_u32(const void* p) {
    uint32_t a;
    asm("{ .reg .u64 t; cvta.to.shared.u64 t, %1; cvt.u32.u64 %0, t; }" : "=r"(a) : "l"(p));
    return a;
}
#define CP16(s, g)   asm volatile("cp.async.cg.shared.global [%0], [%1], 16;" :: "r"(s), "l"(g))
#define CP_COMMIT()  asm volatile("cp.async.commit_group;" ::: "memory")
#define CP_WAIT2()   asm volatile("cp.async.wait_group 2;" ::: "memory")

__device__ __forceinline__ void ldsm4(uint32_t& r0, uint32_t& r1, uint32_t& r2, uint32_t& r3, uint32_t a) {
    asm volatile("ldmatrix.sync.aligned.m8n8.x4.shared.b16 {%0,%1,%2,%3}, [%4];"
        : "=r"(r0), "=r"(r1), "=r"(r2), "=r"(r3) : "r"(a));
}
__device__ __forceinline__ void mma_bf16(float* c, const uint32_t* a, const uint32_t* b) {
    asm volatile("mma.sync.aligned.m16n8k16.row.col.f32.bf16.bf16.f32 "
        "{%0,%1,%2,%3}, {%4,%5,%6,%7}, {%8,%9}, {%0,%1,%2,%3};"
        : "+f"(c[0]), "+f"(c[1]), "+f"(c[2]), "+f"(c[3])
        : "r"(a[0]), "r"(a[1]), "r"(a[2]), "r"(a[3]), "r"(b[0]), "r"(b[1]));
}

// ================= scratch (device globals) =================================
static __device__ __nv_bfloat16 g_qb[8u * 1024 * 512];    // [b][n][m]
static __device__ __nv_bfloat16 g_kb[8u * 1024 * 512];    // [b][n][m]
static __device__ __nv_bfloat16 g_vmn[8u * 512 * 1024];   // [b][m][n]
static __device__ __nv_bfloat16 g_eb[8u * 1024 * 1024];   // bf16 energy
static __device__ __nv_bfloat16 g_attn[8u * 1024 * 1024]; // bf16 attn
static __device__ float         g_o[8u * 1024 * 512];     // == [Cq][W][H]

// ================= kernel 1: fused QKV conv (HFMA2, coalesced stores) =======
__global__ __launch_bounds__(256) void qkv_kernel(
    const float* __restrict__ x,
    const float* __restrict__ Wq, const float* __restrict__ bq,
    const float* __restrict__ Wk, const float* __restrict__ bk,
    const float* __restrict__ Wv, const float* __restrict__ bv)
{
    __shared__ __align__(16) __nv_bfloat162 sW2[3][64][8];
    __shared__ __nv_bfloat162 sb2[24];
    __shared__ __nv_bfloat162 st[3][32][17];
    int tid = threadIdx.x;
    for (int i = tid; i < 512; i += 256) {
        int c = i >> 3, cq = i & 7;
        sW2[0][c][cq] = __float2bfloat162_rn(Wq[cq * 64 + c]);
        sW2[1][c][cq] = __float2bfloat162_rn(Wk[cq * 64 + c]);
        sW2[2][c][cq] = __float2bfloat162_rn(Wv[cq * 64 + c]);
    }
    if (tid < 24) {
        const float* bp = tid < 8 ? bq : (tid < 16 ? bk : bv);
        sb2[tid] = __float2bfloat162_rn(bp[tid & 7]);
    }
    __syncthreads();

    int b   = blockIdx.z;
    int pw  = blockIdx.x;
    int wp0 = (blockIdx.y & 3) * 8;
    int h0  = (blockIdx.y >> 2) * 32;
    int wp_i = tid >> 5, hl = tid & 31;
    int w = (wp0 + wp_i) * 8 + pw;
    int h = h0 + hl;
    const float* xp = x + ((size_t)b << 22) + (w << 8) + h;

    __nv_bfloat162 acc[24];
    #pragma unroll
    for (int i = 0; i < 24; i++) acc[i] = sb2[i];

    #pragma unroll 4
    for (int c = 0; c < 64; c++) {
        float xl = __ldg(xp + ((size_t)c << 16));
        float xh = __ldg(xp + ((size_t)c << 16) + 128);
        __nv_bfloat162 x2 = __floats2bfloat162_rn(xl, xh);
        uint4 uq0 = ((const uint4*)&sW2[0][c][0])[0];
        uint4 uq1 = ((const uint4*)&sW2[0][c][0])[1];
        uint4 uk0 = ((const uint4*)&sW2[1][c][0])[0];
        uint4 uk1 = ((const uint4*)&sW2[1][c][0])[1];
        uint4 uv0 = ((const uint4*)&sW2[2][c][0])[0];
        uint4 uv1 = ((const uint4*)&sW2[2][c][0])[1];
        #define B2(u) (*reinterpret_cast<const __nv_bfloat162*>(&(u)))
        acc[0]  = __hfma2(B2(uq0.x), x2, acc[0]);
        acc[1]  = __hfma2(B2(uq0.y), x2, acc[1]);
        acc[2]  = __hfma2(B2(uq0.z), x2, acc[2]);
        acc[3]  = __hfma2(B2(uq0.w), x2, acc[3]);
        acc[4]  = __hfma2(B2(uq1.x), x2, acc[4]);
        acc[5]  = __hfma2(B2(uq1.y), x2, acc[5]);
        acc[6]  = __hfma2(B2(uq1.z), x2, acc[6]);
        acc[7]  = __hfma2(B2(uq1.w), x2, acc[7]);
        acc[8]  = __hfma2(B2(uk0.x), x2, acc[8]);
        acc[9]  = __hfma2(B2(uk0.y), x2, acc[9]);
        acc[10] = __hfma2(B2(uk0.z), x2, acc[10]);
        acc[11] = __hfma2(B2(uk0.w), x2, acc[11]);
        acc[12] = __hfma2(B2(uk1.x), x2, acc[12]);
        acc[13] = __hfma2(B2(uk1.y), x2, acc[13]);
        acc[14] = __hfma2(B2(uk1.z), x2, acc[14]);
        acc[15] = __hfma2(B2(uk1.w), x2, acc[15]);
        acc[16] = __hfma2(B2(uv0.x), x2, acc[16]);
        acc[17] = __hfma2(B2(uv0.y), x2, acc[17]);
        acc[18] = __hfma2(B2(uv0.z), x2, acc[18]);
        acc[19] = __hfma2(B2(uv0.w), x2, acc[19]);
        acc[20] = __hfma2(B2(uv1.x), x2, acc[20]);
        acc[21] = __hfma2(B2(uv1.y), x2, acc[21]);
        acc[22] = __hfma2(B2(uv1.z), x2, acc[22]);
        acc[23] = __hfma2(B2(uv1.w), x2, acc[23]);
        #undef B2
    }

    int nb = (h0 >> 3) * 64 + pw * 8;
    int nn_w = tid >> 3, mm_w = tid & 7;
    int n_qk = nb + ((nn_w >> 3) << 6) + (nn_w & 7);
    int mm_v = tid >> 5, nl_v = tid & 31;
    int n_v  = nb + ((nl_v >> 3) << 6) + (nl_v & 7);

    __nv_bfloat162* qp = (__nv_bfloat162*)g_qb;
    __nv_bfloat162* kp = (__nv_bfloat162*)g_kb;
    __nv_bfloat16*  vp = g_vmn;

    #pragma unroll
    for (int cq = 0; cq < 8; cq++) {
        __syncthreads();
        st[0][hl][wp_i] = acc[cq];
        st[1][hl][wp_i] = acc[8 + cq];
        st[2][hl][wp_i] = acc[16 + cq];
        __syncthreads();
        size_t qkaddr = (((size_t)b << 10) + n_qk) * 256 + cq * 32 + wp0 + mm_w;
        qp[qkaddr] = st[0][nn_w][mm_w];
        kp[qkaddr] = st[1][nn_w][mm_w];
        __nv_bfloat162 vv = st[2][nl_v][mm_v];
        size_t vaddr = (((size_t)b * 512) + cq * 64 + wp0 * 2 + 2 * mm_v) * 1024 + n_v;
        vp[vaddr]        = __low2bfloat16(vv);
        vp[vaddr + 1024] = __high2bfloat16(vv);
    }
}

// ================= HMMA bf16 NT GEMM: C = alpha * A @ B^T ===================
// 4-stage cp.async pipeline, ONE __syncthreads per stage.
// At stage s: wait_group 2 -> buf s%4 ready; barrier; issue(s+3) writes
// buf (s+3)%4 == (s-1)%4 which all warps finished reading before this barrier.
static constexpr int HLDT  = 40;
static constexpr int HSTG  = 128 * HLDT * 2;     // 10240 B
static constexpr int HBOFF = 4 * HSTG;           // B tiles after 4 A stages
static constexpr int HSMEM = 8 * HSTG;           // 81920 B

template <int K, int LDA, int LDB, int LDC, long SA, long SB, long SC, typename OutT>
__device__ __forceinline__ void hgemm_body(
    const __nv_bfloat16* __restrict__ A, const __nv_bfloat16* __restrict__ B,
    OutT* __restrict__ C, float alpha)
{
    extern __shared__ __align__(16) char smem[];
    uint32_t sbase = smem_u32(smem);
    int tid = threadIdx.x, lane = tid & 31, wid = tid >> 5;
    int wm = wid & 1, wn = wid >> 1;
    A += (size_t)blockIdx.z * SA;
    B += (size_t)blockIdx.z * SB;
    C += (size_t)blockIdx.z * SC;
    int m0 = blockIdx.y * 128, n0 = blockIdx.x * 128;

    auto issue = [&](int s) {
        int buf = s & 3;
        int k0 = s * 32;
        #pragma unroll
        for (int i = 0; i < 4; i++) {
            int c = i * 256 + tid;
            int isB = c >> 9;
            int cc = c & 511;
            int row = cc >> 2;
            int col = (cc & 3) << 3;
            const __nv_bfloat16* g = isB
                ? B + (size_t)(n0 + row) * LDB + k0 + col
                : A + (size_t)(m0 + row) * LDA + k0 + col;
            uint32_t sa = sbase + (isB ? HBOFF : 0) + buf * HSTG + (row * HLDT + col) * 2;
            CP16(sa, g);
        }
        CP_COMMIT();
    };

    constexpr int S = K / 32;
    issue(0); issue(1); issue(2);

    float acc[4][4][4];
    #pragma unroll
    for (int mt = 0; mt < 4; mt++)
        #pragma unroll
        for (int nt = 0; nt < 4; nt++)
            #pragma unroll
            for (int r = 0; r < 4; r++) acc[mt][nt][r] = 0.f;

    uint32_t a_off = ((wm * 64 + (lane & 15)) * HLDT + (lane >> 4) * 8) * 2;
    uint32_t b_off = ((wn * 32 + (lane & 15)) * HLDT + (lane >> 4) * 8) * 2;

    for (int s = 0; s < S; s++) {
        int buf = s & 3;
        CP_WAIT2();
        __syncthreads();
        if (s + 3 < S) issue(s + 3); else CP_COMMIT();
        uint32_t abase = sbase + buf * HSTG + a_off;
        uint32_t bbase = sbase + HBOFF + buf * HSTG + b_off;
        #pragma unroll
        for (int kk = 0; kk < 2; kk++) {
            uint32_t a[4][4], bfr[4][2];
            #pragma unroll
            for (int mt = 0; mt < 4; mt++)
                ldsm4(a[mt][0], a[mt][1], a[mt][2], a[mt][3],
                      abase + (mt * 16 * HLDT + kk * 16) * 2);
            #pragma unroll
            for (int np = 0; np < 2; np++) {
                uint32_t t0, t1, t2, t3;
                ldsm4(t0, t1, t2, t3, bbase + (np * 16 * HLDT + kk * 16) * 2);
                bfr[2 * np][0] = t0;     bfr[2 * np][1] = t2;
                bfr[2 * np + 1][0] = t1; bfr[2 * np + 1][1] = t3;
            }
            #pragma unroll
            for (int mt = 0; mt < 4; mt++)
                #pragma unroll
                for (int nt = 0; nt < 4; nt++)
                    mma_bf16(acc[mt][nt], a[mt], bfr[nt]);
        }
    }

    int rbase = m0 + wm * 64 + (lane >> 2);
    int cbase = n0 + wn * 32 + (lane & 3) * 2;
    #pragma unroll
    for (int mt = 0; mt < 4; mt++)
        #pragma unroll
        for (int nt = 0; nt < 4; nt++) {
            if constexpr (sizeof(OutT) == 2) {
                __nv_bfloat162 v0 = __floats2bfloat162_rn(acc[mt][nt][0] * alpha, acc[mt][nt][1] * alpha);
                __nv_bfloat162 v1 = __floats2bfloat162_rn(acc[mt][nt][2] * alpha, acc[mt][nt][3] * alpha);
                *(__nv_bfloat162*)(C + (size_t)(rbase + mt * 16) * LDC + cbase + nt * 8) = v0;
                *(__nv_bfloat162*)(C + (size_t)(rbase + mt * 16 + 8) * LDC + cbase + nt * 8) = v1;
            } else {
                float2 v0 = { acc[mt][nt][0] * alpha, acc[mt][nt][1] * alpha };
                float2 v1 = { acc[mt][nt][2] * alpha, acc[mt][nt][3] * alpha };
                *(float2*)(C + (size_t)(rbase + mt * 16) * LDC + cbase + nt * 8) = v0;
                *(float2*)(C + (size_t)(rbase + mt * 16 + 8) * LDC + cbase + nt * 8) = v1;
            }
        }
}

// energy(bf16) = (1/32) Q @ K^T
__global__ __launch_bounds__(256, 2) void gemm_qk_kernel()
{
    hgemm_body<512, 512, 512, 1024, 1024l * 512, 1024l * 512, 1024l * 1024, __nv_bfloat16>(
        g_qb, g_kb, g_eb, 1.0f / 32.0f);
}
// O(fp32) = attn @ V[m][n]^T
__global__ __launch_bounds__(256, 2) void gemm_av_kernel()
{
    hgemm_body<1024, 1024, 1024, 512, 1024l * 1024, 512l * 1024, 1024l * 512, float>(
        g_attn, g_vmn, g_o, 1.0f);
}

// ================= softmax: bf16 in -> bf16 out =============================
__global__ __launch_bounds__(256) void softmax_kernel()
{
    size_t row = blockIdx.x;
    const __nv_bfloat162* r = (const __nv_bfloat162*)(g_eb + row * 1024);
    int tid = threadIdx.x, wid = tid >> 5, lid = tid & 31;
    __shared__ float sm[8], ss[8];

    __nv_bfloat162 e0 = r[2 * tid], e1 = r[2 * tid + 1];
    float4 v = { __low2float(e0), __high2float(e0), __low2float(e1), __high2float(e1) };
    float m = fmaxf(fmaxf(v.x, v.y), fmaxf(v.z, v.w));
    #pragma unroll
    for (int o = 16; o; o >>= 1) m = fmaxf(m, __shfl_xor_sync(0xffffffffu, m, o));
    if (lid == 0) sm[wid] = m;
    __syncthreads();
    m = sm[0];
    #pragma unroll
    for (int i = 1; i < 8; i++) m = fmaxf(m, sm[i]);

    v.x = __expf(v.x - m); v.y = __expf(v.y - m);
    v.z = __expf(v.z - m); v.w = __expf(v.w - m);
    float s = (v.x + v.y) + (v.z + v.w);
    #pragma unroll
    for (int o = 16; o; o >>= 1) s += __shfl_xor_sync(0xffffffffu, s, o);
    if (lid == 0) ss[wid] = s;
    __syncthreads();
    s = ss[0];
    #pragma unroll
    for (int i = 1; i < 8; i++) s += ss[i];

    float inv = 1.0f / s;
    __nv_bfloat162* op = (__nv_bfloat162*)(g_attn + row * 1024) + 2 * tid;
    op[0] = __floats2bfloat162_rn(v.x * inv, v.y * inv);
    op[1] = __floats2bfloat162_rn(v.z * inv, v.w * inv);
}

// ================= epilogue: out = gamma*(Wo @ O + bo) + x ==================
__global__ __launch_bounds__(256) void epilogue_kernel(
    const float* __restrict__ x, const float* __restrict__ Wo,
    const float* __restrict__ bo, const float* __restrict__ gamma,
    float* __restrict__ out)
{
    __shared__ __align__(16) float sWo[512];
    __shared__ float sbo[64];
    int tid = threadIdx.x;
    for (int i = tid; i < 512; i += 256) sWo[i] = Wo[i];
    if (tid < 64) sbo[tid] = bo[tid];
    __syncthreads();
    float g = __ldg(gamma);

    int t = blockIdx.x * 256 + tid;
    int b = t >> 16;
    int p = t & 65535;

    float ov[8];
    size_t obase = ((size_t)b << 19) + p;
    #pragma unroll
    for (int cq = 0; cq < 8; cq++) ov[cq] = g_o[obase + ((size_t)cq << 16)];

    size_t xbase = ((size_t)b << 22) + p;
    #pragma unroll 8
    for (int o = 0; o < 64; o++) {
        float4 w0 = *(const float4*)(sWo + o * 8);
        float4 w1 = *(const float4*)(sWo + o * 8 + 4);
        float a = sbo[o];
        a += w0.x * ov[0] + w0.y * ov[1] + w0.z * ov[2] + w0.w * ov[3];
        a += w1.x * ov[4] + w1.y * ov[5] + w1.z * ov[6] + w1.w * ov[7];
        size_t idx = xbase + ((size_t)o << 16);
        out[idx] = g * a + __ldg(x + idx);
    }
}

// ================= launch ===================================================
extern "C" void kernel_launch(void* const* d_in, const int* in_sizes, int n_in,
                              void* d_out, int out_size)
{
    const float* x     = (const float*)d_in[0];
    const float* Wq    = (const float*)d_in[1];
    const float* bq    = (const float*)d_in[2];
    const float* Wk    = (const float*)d_in[3];
    const float* bk    = (const float*)d_in[4];
    const float* Wv    = (const float*)d_in[5];
    const float* bv    = (const float*)d_in[6];
    const float* Wo    = (const float*)d_in[7];
    const float* bo    = (const float*)d_in[8];
    const float* gamma = (const float*)d_in[9];
    float* out = (float*)d_out;

    cudaFuncSetAttribute(gemm_qk_kernel, cudaFuncAttributeMaxDynamicSharedMemorySize, HSMEM);
    cudaFuncSetAttribute(gemm_av_kernel, cudaFuncAttributeMaxDynamicSharedMemorySize, HSMEM);

    dim3 gq(8, 16, 8);
    qkv_kernel<<<gq, 256>>>(x, Wq, bq, Wk, bk, Wv, bv);

    dim3 gqk(8, 8, 8);
    gemm_qk_kernel<<<gqk, 256, HSMEM>>>();

    softmax_kernel<<<8 * 1024, 256>>>();

    dim3 gav(4, 8, 8);
    gemm_av_kernel<<<gav, 256, HSMEM>>>();

    epilogue_kernel<<<2048, 256>>>(x, Wo, bo, gamma, out);
}